// round 11
// baseline (speedup 1.0000x reference)
#include <cuda_runtime.h>
#include <cuda_bf16.h>
#include <math.h>

// Problem constants
#define H   1024
#define IW  512          // moe_intermediate_size
#define E   16
#define T   4096         // B*S tokens
#define P   8192         // T * K pairs
#define ISH 1024         // shared intermediate (I * 2)

// ---------------- device scratch (static globals; no runtime allocation) ----
__device__ int   g_count[16];
__device__ int   g_offsets[17];
__device__ int   g_cursor[16];
__device__ int   g_topk_idx[T * 2];
__device__ float g_topk_w[T * 2];
__device__ int   g_pair_token[P];
__device__ int   g_pos_of[T * 2];
// gate|up concatenated per pair row [P][1024]; after silu kernel, cols [0,512) hold act
__device__ float g_gu[(size_t)P * 1024];
// down-projection per pair row [P][1024]
__device__ float g_down[(size_t)P * 1024];
// shared expert gate|up [T][2048]; after silu kernel, cols [0,1024) hold act
__device__ float g_sgu[(size_t)T * 2048];

// ---------------- small kernels -------------------------------------------
__global__ void k_init() {
    int i = threadIdx.x;
    if (i < 16) g_count[i] = 0;
}

// One block (128 threads) per token: 16 router dots, softmax-top2 closed form.
__global__ void k_router(const float* __restrict__ x,
                         const float* __restrict__ rw) {
    int t = blockIdx.x;
    __shared__ float xs[H];
    __shared__ float sc[16];
    int tid = threadIdx.x;
    const float4* xv = (const float4*)(x + (size_t)t * H);
    ((float4*)xs)[tid]       = xv[tid];
    ((float4*)xs)[tid + 128] = xv[tid + 128];
    __syncthreads();

    int e = tid >> 3, lane = tid & 7;
    const float* w = rw + (size_t)e * H;
    float s = 0.f;
    #pragma unroll 4
    for (int h = lane * 4; h < H; h += 32) {
        float4 a = *(const float4*)(xs + h);
        float4 b = *(const float4*)(w + h);
        s += a.x * b.x + a.y * b.y + a.z * b.z + a.w * b.w;
    }
    #pragma unroll
    for (int o = 4; o; o >>= 1) s += __shfl_down_sync(0xffffffffu, s, o, 8);
    if (lane == 0) sc[e] = s;
    __syncthreads();

    if (tid == 0) {
        int i1 = 0; float s1 = sc[0];
        #pragma unroll
        for (int i = 1; i < 16; i++) if (sc[i] > s1) { s1 = sc[i]; i1 = i; }
        int i2 = -1; float s2 = -3.0e38f;
        #pragma unroll
        for (int i = 0; i < 16; i++) if (i != i1 && sc[i] > s2) { s2 = sc[i]; i2 = i; }
        // normalized top-2 softmax weights: softmax denom cancels
        float r  = expf(s2 - s1);
        float w1 = 1.f / (1.f + r);
        float w2 = r / (1.f + r);
        g_topk_idx[t * 2]     = i1;
        g_topk_idx[t * 2 + 1] = i2;
        g_topk_w[t * 2]       = w1;
        g_topk_w[t * 2 + 1]   = w2;
        atomicAdd(&g_count[i1], 1);
        atomicAdd(&g_count[i2], 1);
    }
}

__global__ void k_scan() {
    if (threadIdx.x == 0) {
        int o = 0;
        for (int e = 0; e < 16; e++) { g_offsets[e] = o; o += g_count[e]; }
        g_offsets[16] = o;
    }
    if (threadIdx.x < 16) g_cursor[threadIdx.x] = 0;
}

__global__ void k_scatter() {
    int t = blockIdx.x * blockDim.x + threadIdx.x;
    if (t >= T) return;
    #pragma unroll
    for (int s = 0; s < 2; s++) {
        int e   = g_topk_idx[t * 2 + s];
        int pos = g_offsets[e] + atomicAdd(&g_cursor[e], 1);
        g_pair_token[pos]  = t;
        g_pos_of[t * 2 + s] = pos;
    }
}

// ---------------- tiled SGEMM core: 128x64 tile, BK=16, 256 threads --------
#define BM 128
#define BN 64
#define BK 16

__device__ __forceinline__ void gemm_core(
    const float* __restrict__ A, int lda,
    const int* __restrict__ rowmap, int row_off, int Mrem,
    const float* __restrict__ Bt, int ldb,
    float* __restrict__ Ct, int ldc, int K)
{
    __shared__ float As[BK][BM + 4];
    __shared__ float Bs[BK][BN];
    int tid = threadIdx.x;

    // A loaders: 2 float4 per thread per k-tile
    int ar = tid >> 2;           // 0..63
    int ak = (tid & 3) << 2;     // 0,4,8,12
    bool v0 = ar < Mrem;
    bool v1 = (ar + 64) < Mrem;
    const float* ap0 = A;
    const float* ap1 = A;
    if (v0) { int r = rowmap ? rowmap[row_off + ar]      : (row_off + ar);      ap0 = A + (size_t)r * lda + ak; }
    if (v1) { int r = rowmap ? rowmap[row_off + ar + 64] : (row_off + ar + 64); ap1 = A + (size_t)r * lda + ak; }

    // B loader: 1 float4 per thread per k-tile
    int bk = tid >> 4;           // 0..15
    int bn = (tid & 15) << 2;    // 0..60
    const float* bp = Bt + (size_t)bk * ldb + bn;

    int tn = (tid & 15) << 2;    // n sub-tile
    int tm = (tid >> 4) << 2;    // m sub-tile (rows tm..tm+3, tm+64..tm+67)

    float acc[8][4];
    #pragma unroll
    for (int i = 0; i < 8; i++)
        #pragma unroll
        for (int j = 0; j < 4; j++) acc[i][j] = 0.f;

    const float4 z4 = make_float4(0.f, 0.f, 0.f, 0.f);
    for (int k0 = 0; k0 < K; k0 += BK) {
        float4 a0 = v0 ? *(const float4*)(ap0 + k0) : z4;
        float4 a1 = v1 ? *(const float4*)(ap1 + k0) : z4;
        float4 b  = *(const float4*)bp;
        bp += (size_t)BK * ldb;

        __syncthreads();
        As[ak + 0][ar] = a0.x; As[ak + 1][ar] = a0.y;
        As[ak + 2][ar] = a0.z; As[ak + 3][ar] = a0.w;
        As[ak + 0][ar + 64] = a1.x; As[ak + 1][ar + 64] = a1.y;
        As[ak + 2][ar + 64] = a1.z; As[ak + 3][ar + 64] = a1.w;
        *(float4*)(&Bs[bk][bn]) = b;
        __syncthreads();

        #pragma unroll
        for (int kk = 0; kk < BK; kk++) {
            float4 t0 = *(const float4*)(&As[kk][tm]);
            float4 t1 = *(const float4*)(&As[kk][tm + 64]);
            float4 t2 = *(const float4*)(&Bs[kk][tn]);
            float a[8] = { t0.x, t0.y, t0.z, t0.w, t1.x, t1.y, t1.z, t1.w };
            float bb[4] = { t2.x, t2.y, t2.z, t2.w };
            #pragma unroll
            for (int i = 0; i < 8; i++)
                #pragma unroll
                for (int j = 0; j < 4; j++)
                    acc[i][j] = fmaf(a[i], bb[j], acc[i][j]);
        }
    }

    #pragma unroll
    for (int i = 0; i < 8; i++) {
        int m = (i < 4) ? (tm + i) : (tm + 64 + i - 4);
        if (m < Mrem) {
            float4 r = make_float4(acc[i][0], acc[i][1], acc[i][2], acc[i][3]);
            *(float4*)(Ct + (size_t)m * ldc + tn) = r;
        }
    }
}

// ---------------- GEMM wrappers -------------------------------------------
// Routed gate|up: gathered rows of x, virtual N=1024 (cols<512 -> gate, else up)
__global__ void __launch_bounds__(256)
k_routed_gateup(const float* __restrict__ x,
                const float* __restrict__ wg,
                const float* __restrict__ wu) {
    int e   = blockIdx.z;
    int seg = g_offsets[e];
    int ne  = g_offsets[e + 1] - seg;
    int mt  = blockIdx.y * BM;
    if (mt >= ne) return;
    int nt  = blockIdx.x * BN;
    const float* B = (nt < IW) ? (wg + (size_t)e * H * IW + nt)
                               : (wu + (size_t)e * H * IW + (nt - IW));
    gemm_core(x, H, g_pair_token, seg + mt, ne - mt,
              B, IW,
              g_gu + (size_t)(seg + mt) * 1024 + nt, 1024, H);
}

// In-place SiLU(gate)*up for routed pairs: act lands in cols [0,512)
__global__ void k_silu_routed() {
    int idx = blockIdx.x * blockDim.x + threadIdx.x;
    if (idx >= P * IW) return;
    int p = idx >> 9, i = idx & 511;
    float g = g_gu[(size_t)p * 1024 + i];
    float u = g_gu[(size_t)p * 1024 + 512 + i];
    g_gu[(size_t)p * 1024 + i] = g / (1.f + expf(-g)) * u;
}

// Routed down: act rows (stride 1024, K=512) x Wd_e -> g_down (unscaled)
__global__ void __launch_bounds__(256)
k_routed_down(const float* __restrict__ wd) {
    int e   = blockIdx.z;
    int seg = g_offsets[e];
    int ne  = g_offsets[e + 1] - seg;
    int mt  = blockIdx.y * BM;
    if (mt >= ne) return;
    int nt  = blockIdx.x * BN;
    gemm_core(g_gu, 1024, nullptr, seg + mt, ne - mt,
              wd + (size_t)e * IW * H + nt, H,
              g_down + (size_t)(seg + mt) * 1024 + nt, 1024, IW);
}

// Shared gate|up: x direct, virtual N=2048
__global__ void __launch_bounds__(256)
k_shared_gateup(const float* __restrict__ x,
                const float* __restrict__ sg,
                const float* __restrict__ su) {
    int mt = blockIdx.y * BM;
    int nt = blockIdx.x * BN;
    const float* B = (nt < ISH) ? (sg + nt) : (su + (nt - ISH));
    gemm_core(x, H, nullptr, mt, T - mt,
              B, ISH,
              g_sgu + (size_t)mt * 2048 + nt, 2048, H);
}

__global__ void k_silu_shared() {
    int idx = blockIdx.x * blockDim.x + threadIdx.x;
    if (idx >= T * ISH) return;
    int t = idx >> 10, i = idx & 1023;
    float g = g_sgu[(size_t)t * 2048 + i];
    float u = g_sgu[(size_t)t * 2048 + 1024 + i];
    g_sgu[(size_t)t * 2048 + i] = g / (1.f + expf(-g)) * u;
}

// Shared down: writes the shared-expert contribution straight into out ("=")
__global__ void __launch_bounds__(256)
k_shared_down(const float* __restrict__ sd, float* __restrict__ out) {
    int mt = blockIdx.y * BM;
    int nt = blockIdx.x * BN;
    gemm_core(g_sgu, 2048, nullptr, mt, T - mt,
              sd + nt, H,
              out + (size_t)mt * H + nt, H, ISH);
}

// out += w1*down[p1] + w2*down[p2]  (one thread per element -> deterministic)
__global__ void k_combine(float* __restrict__ out) {
    int idx = blockIdx.x * blockDim.x + threadIdx.x;
    if (idx >= T * H) return;
    int t = idx >> 10, h = idx & 1023;
    float r = out[idx];
    r += g_topk_w[t * 2]     * g_down[(size_t)g_pos_of[t * 2]     * 1024 + h];
    r += g_topk_w[t * 2 + 1] * g_down[(size_t)g_pos_of[t * 2 + 1] * 1024 + h];
    out[idx] = r;
}

// ---------------- launch ---------------------------------------------------
extern "C" void kernel_launch(void* const* d_in, const int* in_sizes, int n_in,
                              void* d_out, int out_size) {
    const float* x  = (const float*)d_in[0];   // [T, H]
    const float* rw = (const float*)d_in[1];   // [E, H]
    const float* wg = (const float*)d_in[2];   // [E, H, I]
    const float* wu = (const float*)d_in[3];   // [E, H, I]
    const float* wd = (const float*)d_in[4];   // [E, I, H]
    const float* sg = (const float*)d_in[5];   // [H, IS]
    const float* su = (const float*)d_in[6];   // [H, IS]
    const float* sd = (const float*)d_in[7];   // [IS, H]
    float* out = (float*)d_out;                // [T, H]

    // routing
    k_init<<<1, 32>>>();
    k_router<<<T, 128>>>(x, rw);
    k_scan<<<1, 32>>>();
    k_scatter<<<16, 256>>>();

    // shared expert (writes out with "=")
    k_shared_gateup<<<dim3(2048 / BN, T / BM, 1), 256>>>(x, sg, su);
    k_silu_shared<<<(T * ISH + 255) / 256, 256>>>();
    k_shared_down<<<dim3(H / BN, T / BM, 1), 256>>>(sd, out);

    // routed experts
    k_routed_gateup<<<dim3(1024 / BN, T / BM, E), 256>>>(x, wg, wu);
    k_silu_routed<<<(P * IW + 255) / 256, 256>>>();
    k_routed_down<<<dim3(H / BN, T / BM, E), 256>>>(wd);

    // final combine
    k_combine<<<(T * H + 255) / 256, 256>>>(out);
}

// round 12
// speedup vs baseline: 1.7725x; 1.7725x over previous
#include <cuda_runtime.h>
#include <cuda_bf16.h>
#include <math.h>
#include <stdint.h>

// Problem constants
#define H   1024
#define IW  512          // moe_intermediate_size
#define E   16
#define T   4096         // B*S tokens
#define P   8192         // T * K pairs
#define ISH 1024         // shared intermediate (I * 2)

// ---------------- device scratch ----------------
__device__ int   g_count[16];
__device__ int   g_offsets[17];
__device__ int   g_cursor[16];
__device__ int   g_topk_idx[T * 2];
__device__ float g_topk_w[T * 2];
__device__ int   g_pair_token[P];
__device__ int   g_pos_of[T * 2];
__device__ float g_act[(size_t)P * 512];    // routed silu(gate)*up, expert-grouped rows
__device__ float g_down[(size_t)P * 1024];  // routed down output (unscaled)
__device__ float g_sact[(size_t)T * 1024];  // shared silu(gate)*up

// ---------------- routing (unchanged, passing) ----------------
__global__ void k_init() {
    int i = threadIdx.x;
    if (i < 16) g_count[i] = 0;
}

__global__ void k_router(const float* __restrict__ x,
                         const float* __restrict__ rw) {
    int t = blockIdx.x;
    __shared__ float xs[H];
    __shared__ float sc[16];
    int tid = threadIdx.x;
    const float4* xv = (const float4*)(x + (size_t)t * H);
    ((float4*)xs)[tid]       = xv[tid];
    ((float4*)xs)[tid + 128] = xv[tid + 128];
    __syncthreads();

    int e = tid >> 3, lane = tid & 7;
    const float* w = rw + (size_t)e * H;
    float s = 0.f;
    #pragma unroll 4
    for (int h = lane * 4; h < H; h += 32) {
        float4 a = *(const float4*)(xs + h);
        float4 b = *(const float4*)(w + h);
        s += a.x * b.x + a.y * b.y + a.z * b.z + a.w * b.w;
    }
    #pragma unroll
    for (int o = 4; o; o >>= 1) s += __shfl_down_sync(0xffffffffu, s, o, 8);
    if (lane == 0) sc[e] = s;
    __syncthreads();

    if (tid == 0) {
        int i1 = 0; float s1 = sc[0];
        #pragma unroll
        for (int i = 1; i < 16; i++) if (sc[i] > s1) { s1 = sc[i]; i1 = i; }
        int i2 = -1; float s2 = -3.0e38f;
        #pragma unroll
        for (int i = 0; i < 16; i++) if (i != i1 && sc[i] > s2) { s2 = sc[i]; i2 = i; }
        float r  = expf(s2 - s1);
        float w1 = 1.f / (1.f + r);
        float w2 = r / (1.f + r);
        g_topk_idx[t * 2]     = i1;
        g_topk_idx[t * 2 + 1] = i2;
        g_topk_w[t * 2]       = w1;
        g_topk_w[t * 2 + 1]   = w2;
        atomicAdd(&g_count[i1], 1);
        atomicAdd(&g_count[i2], 1);
    }
}

__global__ void k_scan() {
    if (threadIdx.x == 0) {
        int o = 0;
        for (int e = 0; e < 16; e++) { g_offsets[e] = o; o += g_count[e]; }
        g_offsets[16] = o;
    }
    if (threadIdx.x < 16) g_cursor[threadIdx.x] = 0;
}

__global__ void k_scatter() {
    int t = blockIdx.x * blockDim.x + threadIdx.x;
    if (t >= T) return;
    #pragma unroll
    for (int s = 0; s < 2; s++) {
        int e   = g_topk_idx[t * 2 + s];
        int pos = g_offsets[e] + atomicAdd(&g_cursor[e], 1);
        g_pair_token[pos]   = t;
        g_pos_of[t * 2 + s] = pos;
    }
}

// ---------------- TF32 tensor-core GEMM core ----------------
// Tile: BM=128 x BN=64 x BK=32, 256 threads = 8 warps (4m x 2n), warp tile 32x32.
// mma.sync.aligned.m16n8k8 tf32: 2 m-tiles x 4 n-tiles per warp per k-step.
#define BM 128
#define BN 64
#define BK 32
#define ASTR 36   // As row stride (words): frag loads bank-conflict-free
#define BSTR 68   // Bs row stride (words): frag loads bank-conflict-free

__device__ __forceinline__ uint32_t f2tf(float f) {
    uint32_t r; asm("cvt.rna.tf32.f32 %0, %1;" : "=r"(r) : "f"(f)); return r;
}

__device__ __forceinline__ void mma8(float c[4], const uint32_t a[4], const uint32_t b[2]) {
    asm volatile(
        "mma.sync.aligned.m16n8k8.row.col.f32.tf32.tf32.f32 "
        "{%0,%1,%2,%3}, {%4,%5,%6,%7}, {%8,%9}, {%0,%1,%2,%3};"
        : "+f"(c[0]), "+f"(c[1]), "+f"(c[2]), "+f"(c[3])
        : "r"(a[0]), "r"(a[1]), "r"(a[2]), "r"(a[3]), "r"(b[0]), "r"(b[1]));
}

__device__ __forceinline__ float silu_mul(float g, float u) {
    return g / (1.f + expf(-g)) * u;
}

// FUSED=true : gate/up interleaved GEMM with in-register SiLU epilogue.
//   B0 = gate weights, B1 = up weights (both [K, ldb] row-major, col base nbase,
//   block covers cols [nbase, nbase+32) of each). C = act, width ldc, cols
//   [nbase, nbase+32).
// FUSED=false: plain GEMM, B0 only, block covers C cols [nbase, nbase+64).
template<bool FUSED>
__device__ __forceinline__ void mma_gemm(
    const float* __restrict__ A, int lda,
    const int* __restrict__ rowmap, int row_off, int Mrem,
    const float* __restrict__ B0, const float* __restrict__ B1, int ldb, int nbase,
    float* __restrict__ C, int ldc, int K)
{
    __shared__ uint32_t As[BM * ASTR];
    __shared__ uint32_t Bs[BK * BSTR];

    int tid  = threadIdx.x;
    int warp = tid >> 5, lane = tid & 31;
    int wm = warp >> 1, wn = warp & 1;
    int g  = lane >> 2, t0 = lane & 3;
    int mb = wm * 32,  nb = wn * 32;

    // A loader: thread -> (row ar, 4 float4 chunks at k-offset af*4..)
    int ar = tid >> 1;
    int af = (tid & 1) * 4;
    bool aval = ar < Mrem;
    const float* aptr = A;
    if (aval) {
        int r = rowmap ? rowmap[row_off + ar] : (row_off + ar);
        aptr = A + (size_t)r * lda;
    }

    // B loader: thread -> (k-row bk, 2 float4 chunks)
    int bk  = tid >> 3;
    int bf2 = (tid & 7) * 2;
    const float* bptr[2];
    #pragma unroll
    for (int j = 0; j < 2; j++) {
        int sc = (bf2 + j) * 4;
        if (FUSED) {
            int q = sc >> 4, rem = sc & 15;
            const float* Bsel = (q & 1) ? B1 : B0;
            bptr[j] = Bsel + (size_t)bk * ldb + nbase + ((q >> 1) << 4) + rem;
        } else {
            bptr[j] = B0 + (size_t)bk * ldb + nbase + sc;
        }
    }

    float acc[2][4][4];
    #pragma unroll
    for (int i = 0; i < 2; i++)
        #pragma unroll
        for (int j = 0; j < 4; j++)
            #pragma unroll
            for (int l = 0; l < 4; l++) acc[i][j][l] = 0.f;

    const float4 z4 = make_float4(0.f, 0.f, 0.f, 0.f);
    for (int k0 = 0; k0 < K; k0 += BK) {
        float4 av[4], bv[2];
        #pragma unroll
        for (int j = 0; j < 4; j++)
            av[j] = aval ? *(const float4*)(aptr + k0 + (af + j) * 4) : z4;
        #pragma unroll
        for (int j = 0; j < 2; j++)
            bv[j] = *(const float4*)(bptr[j] + (size_t)k0 * ldb);

        __syncthreads();
        #pragma unroll
        for (int j = 0; j < 4; j++) {
            uint32_t* d = &As[ar * ASTR + (af + j) * 4];
            d[0] = f2tf(av[j].x); d[1] = f2tf(av[j].y);
            d[2] = f2tf(av[j].z); d[3] = f2tf(av[j].w);
        }
        #pragma unroll
        for (int j = 0; j < 2; j++) {
            uint32_t* d = &Bs[bk * BSTR + (bf2 + j) * 4];
            d[0] = f2tf(bv[j].x); d[1] = f2tf(bv[j].y);
            d[2] = f2tf(bv[j].z); d[3] = f2tf(bv[j].w);
        }
        __syncthreads();

        #pragma unroll
        for (int ks = 0; ks < 4; ks++) {
            int kb = ks * 8;
            uint32_t afr[2][4];
            #pragma unroll
            for (int mt = 0; mt < 2; mt++) {
                int r = mb + mt * 16 + g;
                afr[mt][0] = As[r * ASTR + kb + t0];
                afr[mt][1] = As[(r + 8) * ASTR + kb + t0];
                afr[mt][2] = As[r * ASTR + kb + t0 + 4];
                afr[mt][3] = As[(r + 8) * ASTR + kb + t0 + 4];
            }
            #pragma unroll
            for (int nt = 0; nt < 4; nt++) {
                uint32_t bfr[2];
                bfr[0] = Bs[(kb + t0) * BSTR + nb + nt * 8 + g];
                bfr[1] = Bs[(kb + t0 + 4) * BSTR + nb + nt * 8 + g];
                mma8(acc[0][nt], afr[0], bfr);
                mma8(acc[1][nt], afr[1], bfr);
            }
        }
    }

    // epilogue
    #pragma unroll
    for (int mt = 0; mt < 2; mt++) {
        int r0 = mb + mt * 16 + g;
        int r1 = r0 + 8;
        if (FUSED) {
            #pragma unroll
            for (int nt = 0; nt < 2; nt++) {
                int c = nbase + (wn << 4) + nt * 8 + 2 * t0;
                float a00 = silu_mul(acc[mt][nt][0], acc[mt][nt + 2][0]);
                float a01 = silu_mul(acc[mt][nt][1], acc[mt][nt + 2][1]);
                float a10 = silu_mul(acc[mt][nt][2], acc[mt][nt + 2][2]);
                float a11 = silu_mul(acc[mt][nt][3], acc[mt][nt + 2][3]);
                if (r0 < Mrem) *(float2*)(C + (size_t)r0 * ldc + c) = make_float2(a00, a01);
                if (r1 < Mrem) *(float2*)(C + (size_t)r1 * ldc + c) = make_float2(a10, a11);
            }
        } else {
            #pragma unroll
            for (int nt = 0; nt < 4; nt++) {
                int c = nbase + nb + nt * 8 + 2 * t0;
                if (r0 < Mrem)
                    *(float2*)(C + (size_t)r0 * ldc + c) = make_float2(acc[mt][nt][0], acc[mt][nt][1]);
                if (r1 < Mrem)
                    *(float2*)(C + (size_t)r1 * ldc + c) = make_float2(acc[mt][nt][2], acc[mt][nt][3]);
            }
        }
    }
}

// ---------------- GEMM kernel wrappers ----------------
__global__ void __launch_bounds__(256)
k_routed_gateup(const float* __restrict__ x,
                const float* __restrict__ wg,
                const float* __restrict__ wu) {
    int e   = blockIdx.z;
    int seg = g_offsets[e];
    int ne  = g_offsets[e + 1] - seg;
    int mt  = blockIdx.y * BM;
    if (mt >= ne) return;
    int nbase = blockIdx.x * 32;
    mma_gemm<true>(x, H, g_pair_token, seg + mt, ne - mt,
                   wg + (size_t)e * H * IW, wu + (size_t)e * H * IW, IW, nbase,
                   g_act + (size_t)(seg + mt) * IW, IW, H);
}

__global__ void __launch_bounds__(256)
k_routed_down(const float* __restrict__ wd) {
    int e   = blockIdx.z;
    int seg = g_offsets[e];
    int ne  = g_offsets[e + 1] - seg;
    int mt  = blockIdx.y * BM;
    if (mt >= ne) return;
    int nbase = blockIdx.x * BN;
    mma_gemm<false>(g_act, IW, nullptr, seg + mt, ne - mt,
                    wd + (size_t)e * IW * H, nullptr, H, nbase,
                    g_down + (size_t)(seg + mt) * 1024, 1024, IW);
}

__global__ void __launch_bounds__(256)
k_shared_gateup(const float* __restrict__ x,
                const float* __restrict__ sg,
                const float* __restrict__ su) {
    int mt = blockIdx.y * BM;
    int nbase = blockIdx.x * 32;
    mma_gemm<true>(x, H, nullptr, mt, T - mt,
                   sg, su, ISH, nbase,
                   g_sact + (size_t)mt * ISH, ISH, H);
}

__global__ void __launch_bounds__(256)
k_shared_down(const float* __restrict__ sd, float* __restrict__ out) {
    int mt = blockIdx.y * BM;
    int nbase = blockIdx.x * BN;
    mma_gemm<false>(g_sact, ISH, nullptr, mt, T - mt,
                    sd, nullptr, H, nbase,
                    out + (size_t)mt * H, H, ISH);
}

// out += w1*down[p1] + w2*down[p2]  (one thread per element -> deterministic)
__global__ void k_combine(float* __restrict__ out) {
    int idx = blockIdx.x * blockDim.x + threadIdx.x;
    if (idx >= T * H) return;
    int t = idx >> 10, h = idx & 1023;
    float r = out[idx];
    r += g_topk_w[t * 2]     * g_down[(size_t)g_pos_of[t * 2]     * 1024 + h];
    r += g_topk_w[t * 2 + 1] * g_down[(size_t)g_pos_of[t * 2 + 1] * 1024 + h];
    out[idx] = r;
}

// ---------------- launch ----------------
extern "C" void kernel_launch(void* const* d_in, const int* in_sizes, int n_in,
                              void* d_out, int out_size) {
    const float* x  = (const float*)d_in[0];   // [T, H]
    const float* rw = (const float*)d_in[1];   // [E, H]
    const float* wg = (const float*)d_in[2];   // [E, H, I]
    const float* wu = (const float*)d_in[3];   // [E, H, I]
    const float* wd = (const float*)d_in[4];   // [E, I, H]
    const float* sg = (const float*)d_in[5];   // [H, IS]
    const float* su = (const float*)d_in[6];   // [H, IS]
    const float* sd = (const float*)d_in[7];   // [IS, H]
    float* out = (float*)d_out;                // [T, H]

    // routing
    k_init<<<1, 32>>>();
    k_router<<<T, 128>>>(x, rw);
    k_scan<<<1, 32>>>();
    k_scatter<<<16, 256>>>();

    // shared expert (writes out with "=")
    k_shared_gateup<<<dim3(ISH / 32, T / BM, 1), 256>>>(x, sg, su);
    k_shared_down<<<dim3(H / BN, T / BM, 1), 256>>>(sd, out);

    // routed experts (expert-grouped)
    k_routed_gateup<<<dim3(IW / 32, T / BM, E), 256>>>(x, wg, wu);
    k_routed_down<<<dim3(H / BN, T / BM, E), 256>>>(wd);

    // final combine
    k_combine<<<(T * H + 255) / 256, 256>>>(out);
}

// round 13
// speedup vs baseline: 1.8067x; 1.0193x over previous
#include <cuda_runtime.h>
#include <cuda_bf16.h>
#include <math.h>
#include <stdint.h>

// Problem constants
#define H   1024
#define IW  512          // moe_intermediate_size
#define E   16
#define T   4096         // B*S tokens
#define P   8192         // T * K pairs
#define ISH 1024         // shared intermediate (I * 2)

// ---------------- device scratch ----------------
__device__ int   g_count[16];
__device__ int   g_offsets[17];
__device__ int   g_cursor[16];
__device__ int   g_topk_idx[T * 2];
__device__ float g_topk_w[T * 2];
__device__ int   g_pair_token[P];
__device__ int   g_pos_of[T * 2];
__device__ float g_act[(size_t)P * 512];    // routed silu(gate)*up, expert-grouped rows
__device__ float g_down[(size_t)P * 1024];  // routed down output (unscaled)
__device__ float g_sact[(size_t)T * 1024];  // shared silu(gate)*up

// ---------------- routing (unchanged, passing) ----------------
__global__ void k_init() {
    int i = threadIdx.x;
    if (i < 16) g_count[i] = 0;
}

__global__ void k_router(const float* __restrict__ x,
                         const float* __restrict__ rw) {
    int t = blockIdx.x;
    __shared__ float xs[H];
    __shared__ float sc[16];
    int tid = threadIdx.x;
    const float4* xv = (const float4*)(x + (size_t)t * H);
    ((float4*)xs)[tid]       = xv[tid];
    ((float4*)xs)[tid + 128] = xv[tid + 128];
    __syncthreads();

    int e = tid >> 3, lane = tid & 7;
    const float* w = rw + (size_t)e * H;
    float s = 0.f;
    #pragma unroll 4
    for (int h = lane * 4; h < H; h += 32) {
        float4 a = *(const float4*)(xs + h);
        float4 b = *(const float4*)(w + h);
        s += a.x * b.x + a.y * b.y + a.z * b.z + a.w * b.w;
    }
    #pragma unroll
    for (int o = 4; o; o >>= 1) s += __shfl_down_sync(0xffffffffu, s, o, 8);
    if (lane == 0) sc[e] = s;
    __syncthreads();

    if (tid == 0) {
        int i1 = 0; float s1 = sc[0];
        #pragma unroll
        for (int i = 1; i < 16; i++) if (sc[i] > s1) { s1 = sc[i]; i1 = i; }
        int i2 = -1; float s2 = -3.0e38f;
        #pragma unroll
        for (int i = 0; i < 16; i++) if (i != i1 && sc[i] > s2) { s2 = sc[i]; i2 = i; }
        float r  = expf(s2 - s1);
        float w1 = 1.f / (1.f + r);
        float w2 = r / (1.f + r);
        g_topk_idx[t * 2]     = i1;
        g_topk_idx[t * 2 + 1] = i2;
        g_topk_w[t * 2]       = w1;
        g_topk_w[t * 2 + 1]   = w2;
        atomicAdd(&g_count[i1], 1);
        atomicAdd(&g_count[i2], 1);
    }
}

__global__ void k_scan() {
    if (threadIdx.x == 0) {
        int o = 0;
        for (int e = 0; e < 16; e++) { g_offsets[e] = o; o += g_count[e]; }
        g_offsets[16] = o;
    }
    if (threadIdx.x < 16) g_cursor[threadIdx.x] = 0;
}

__global__ void k_scatter() {
    int t = blockIdx.x * blockDim.x + threadIdx.x;
    if (t >= T) return;
    #pragma unroll
    for (int s = 0; s < 2; s++) {
        int e   = g_topk_idx[t * 2 + s];
        int pos = g_offsets[e] + atomicAdd(&g_cursor[e], 1);
        g_pair_token[pos]   = t;
        g_pos_of[t * 2 + s] = pos;
    }
}

// ---------------- TF32 tensor-core GEMM core (double-buffered) ----------------
// Tile: BM=128 x BN=64 x BK=16, 256 threads = 8 warps (4m x 2n), warp tile 32x32.
// Double-buffered smem: compute buf[s] while tile i+1's global loads fly;
// one __syncthreads per k-iter.
#define BM 128
#define BN 64
#define BK 16
#define ASTR 20   // 20 mod 32 = 4  -> A frag LDS conflict-free (g*20+t0 perm)
#define BSTR 72   // 72 mod 32 = 8  -> B frag LDS conflict-free (t0*8+g perm)

__device__ __forceinline__ uint32_t f2tf(float f) {
    uint32_t r; asm("cvt.rna.tf32.f32 %0, %1;" : "=r"(r) : "f"(f)); return r;
}

__device__ __forceinline__ void mma8(float c[4], const uint32_t a[4], const uint32_t b[2]) {
    asm volatile(
        "mma.sync.aligned.m16n8k8.row.col.f32.tf32.tf32.f32 "
        "{%0,%1,%2,%3}, {%4,%5,%6,%7}, {%8,%9}, {%0,%1,%2,%3};"
        : "+f"(c[0]), "+f"(c[1]), "+f"(c[2]), "+f"(c[3])
        : "r"(a[0]), "r"(a[1]), "r"(a[2]), "r"(a[3]), "r"(b[0]), "r"(b[1]));
}

__device__ __forceinline__ float silu_mul(float g, float u) {
    return g / (1.f + expf(-g)) * u;
}

// FUSED=true : gate/up interleaved (virtual 64 cols = 32 gate + 32 up chunks of
//   16), in-register SiLU epilogue writes 32 act cols at [nbase, nbase+32).
// FUSED=false: plain GEMM, C cols [nbase, nbase+64).
template<bool FUSED>
__device__ __forceinline__ void mma_gemm(
    const float* __restrict__ A, int lda,
    const int* __restrict__ rowmap, int row_off, int Mrem,
    const float* __restrict__ B0, const float* __restrict__ B1, int ldb, int nbase,
    float* __restrict__ C, int ldc, int K)
{
    __shared__ uint32_t As[2][BM * ASTR];
    __shared__ uint32_t Bs[2][BK * BSTR];

    int tid  = threadIdx.x;
    int warp = tid >> 5, lane = tid & 31;
    int wm = warp >> 1, wn = warp & 1;
    int g  = lane >> 2, t0 = lane & 3;
    int mb = wm * 32,  nb = wn * 32;

    // A loader: thread -> row ar, k-cols ac..ac+7 (2 float4)
    int ar = tid >> 1;
    int ac = (tid & 1) * 8;
    bool aval = ar < Mrem;
    const float* aptr = A;
    if (aval) {
        int r = rowmap ? rowmap[row_off + ar] : (row_off + ar);
        aptr = A + (size_t)r * lda + ac;
    }

    // B loader: thread -> k-row bk, 4 cols (1 float4)
    int bk  = tid >> 4;
    int bn4 = (tid & 15) * 4;
    const float* bptr;
    if (FUSED) {
        int q = bn4 >> 4, within = bn4 & 15;
        const float* Bsel = (q & 1) ? B1 : B0;
        bptr = Bsel + (size_t)bk * ldb + nbase + ((q >> 1) << 4) + within;
    } else {
        bptr = B0 + (size_t)bk * ldb + nbase + bn4;
    }

    float4 av0, av1, bv;
    const float4 z4 = make_float4(0.f, 0.f, 0.f, 0.f);

    float acc[2][4][4];
    #pragma unroll
    for (int i = 0; i < 2; i++)
        #pragma unroll
        for (int j = 0; j < 4; j++)
            #pragma unroll
            for (int l = 0; l < 4; l++) acc[i][j][l] = 0.f;

    const int niter = K / BK;

    // prologue: tile 0 -> buf 0; start tile 1 loads
    av0 = aval ? *(const float4*)(aptr)     : z4;
    av1 = aval ? *(const float4*)(aptr + 4) : z4;
    bv  = *(const float4*)(bptr);
    {
        uint32_t* d = &As[0][ar * ASTR + ac];
        d[0]=f2tf(av0.x); d[1]=f2tf(av0.y); d[2]=f2tf(av0.z); d[3]=f2tf(av0.w);
        d[4]=f2tf(av1.x); d[5]=f2tf(av1.y); d[6]=f2tf(av1.z); d[7]=f2tf(av1.w);
        uint32_t* e2 = &Bs[0][bk * BSTR + bn4];
        e2[0]=f2tf(bv.x); e2[1]=f2tf(bv.y); e2[2]=f2tf(bv.z); e2[3]=f2tf(bv.w);
    }
    __syncthreads();
    if (niter > 1) {
        av0 = aval ? *(const float4*)(aptr + BK)     : z4;
        av1 = aval ? *(const float4*)(aptr + BK + 4) : z4;
        bv  = *(const float4*)(bptr + (size_t)BK * ldb);
    }

    int s = 0;
    for (int it = 0; it < niter; it++) {
        // compute tile it from buf[s] (tile it+1 loads are in flight)
        #pragma unroll
        for (int ks = 0; ks < 2; ks++) {
            int kb = ks * 8;
            uint32_t afr[2][4];
            #pragma unroll
            for (int mt = 0; mt < 2; mt++) {
                int r = mb + mt * 16 + g;
                afr[mt][0] = As[s][r * ASTR + kb + t0];
                afr[mt][1] = As[s][(r + 8) * ASTR + kb + t0];
                afr[mt][2] = As[s][r * ASTR + kb + t0 + 4];
                afr[mt][3] = As[s][(r + 8) * ASTR + kb + t0 + 4];
            }
            #pragma unroll
            for (int nt = 0; nt < 4; nt++) {
                uint32_t bfr[2];
                bfr[0] = Bs[s][(kb + t0) * BSTR + nb + nt * 8 + g];
                bfr[1] = Bs[s][(kb + t0 + 4) * BSTR + nb + nt * 8 + g];
                mma8(acc[0][nt], afr[0], bfr);
                mma8(acc[1][nt], afr[1], bfr);
            }
        }
        if (it + 1 < niter) {
            // stage tile it+1 into buf[s^1]
            uint32_t* d = &As[s ^ 1][ar * ASTR + ac];
            d[0]=f2tf(av0.x); d[1]=f2tf(av0.y); d[2]=f2tf(av0.z); d[3]=f2tf(av0.w);
            d[4]=f2tf(av1.x); d[5]=f2tf(av1.y); d[6]=f2tf(av1.z); d[7]=f2tf(av1.w);
            uint32_t* e2 = &Bs[s ^ 1][bk * BSTR + bn4];
            e2[0]=f2tf(bv.x); e2[1]=f2tf(bv.y); e2[2]=f2tf(bv.z); e2[3]=f2tf(bv.w);
            __syncthreads();
            s ^= 1;
            if (it + 2 < niter) {
                int k0 = (it + 2) * BK;
                av0 = aval ? *(const float4*)(aptr + k0)     : z4;
                av1 = aval ? *(const float4*)(aptr + k0 + 4) : z4;
                bv  = *(const float4*)(bptr + (size_t)k0 * ldb);
            }
        }
    }

    // epilogue
    #pragma unroll
    for (int mt = 0; mt < 2; mt++) {
        int r0 = mb + mt * 16 + g;
        int r1 = r0 + 8;
        if (FUSED) {
            #pragma unroll
            for (int nt = 0; nt < 2; nt++) {
                int c = nbase + (wn << 4) + nt * 8 + 2 * t0;
                float a00 = silu_mul(acc[mt][nt][0], acc[mt][nt + 2][0]);
                float a01 = silu_mul(acc[mt][nt][1], acc[mt][nt + 2][1]);
                float a10 = silu_mul(acc[mt][nt][2], acc[mt][nt + 2][2]);
                float a11 = silu_mul(acc[mt][nt][3], acc[mt][nt + 2][3]);
                if (r0 < Mrem) *(float2*)(C + (size_t)r0 * ldc + c) = make_float2(a00, a01);
                if (r1 < Mrem) *(float2*)(C + (size_t)r1 * ldc + c) = make_float2(a10, a11);
            }
        } else {
            #pragma unroll
            for (int nt = 0; nt < 4; nt++) {
                int c = nbase + nb + nt * 8 + 2 * t0;
                if (r0 < Mrem)
                    *(float2*)(C + (size_t)r0 * ldc + c) = make_float2(acc[mt][nt][0], acc[mt][nt][1]);
                if (r1 < Mrem)
                    *(float2*)(C + (size_t)r1 * ldc + c) = make_float2(acc[mt][nt][2], acc[mt][nt][3]);
            }
        }
    }
}

// ---------------- GEMM kernel wrappers ----------------
__global__ void __launch_bounds__(256, 2)
k_routed_gateup(const float* __restrict__ x,
                const float* __restrict__ wg,
                const float* __restrict__ wu) {
    int e   = blockIdx.z;
    int seg = g_offsets[e];
    int ne  = g_offsets[e + 1] - seg;
    int mt  = blockIdx.y * BM;
    if (mt >= ne) return;
    int nbase = blockIdx.x * 32;
    mma_gemm<true>(x, H, g_pair_token, seg + mt, ne - mt,
                   wg + (size_t)e * H * IW, wu + (size_t)e * H * IW, IW, nbase,
                   g_act + (size_t)(seg + mt) * IW, IW, H);
}

__global__ void __launch_bounds__(256, 2)
k_routed_down(const float* __restrict__ wd) {
    int e   = blockIdx.z;
    int seg = g_offsets[e];
    int ne  = g_offsets[e + 1] - seg;
    int mt  = blockIdx.y * BM;
    if (mt >= ne) return;
    int nbase = blockIdx.x * BN;
    mma_gemm<false>(g_act, IW, nullptr, seg + mt, ne - mt,
                    wd + (size_t)e * IW * H, nullptr, H, nbase,
                    g_down + (size_t)(seg + mt) * 1024, 1024, IW);
}

__global__ void __launch_bounds__(256, 2)
k_shared_gateup(const float* __restrict__ x,
                const float* __restrict__ sg,
                const float* __restrict__ su) {
    int mt = blockIdx.y * BM;
    int nbase = blockIdx.x * 32;
    mma_gemm<true>(x, H, nullptr, mt, T - mt,
                   sg, su, ISH, nbase,
                   g_sact + (size_t)mt * ISH, ISH, H);
}

__global__ void __launch_bounds__(256, 2)
k_shared_down(const float* __restrict__ sd, float* __restrict__ out) {
    int mt = blockIdx.y * BM;
    int nbase = blockIdx.x * BN;
    mma_gemm<false>(g_sact, ISH, nullptr, mt, T - mt,
                    sd, nullptr, H, nbase,
                    out + (size_t)mt * H, H, ISH);
}

// out += w1*down[p1] + w2*down[p2]  (one thread per element -> deterministic)
__global__ void k_combine(float* __restrict__ out) {
    int idx = blockIdx.x * blockDim.x + threadIdx.x;
    if (idx >= T * H) return;
    int t = idx >> 10, h = idx & 1023;
    float r = out[idx];
    r += g_topk_w[t * 2]     * g_down[(size_t)g_pos_of[t * 2]     * 1024 + h];
    r += g_topk_w[t * 2 + 1] * g_down[(size_t)g_pos_of[t * 2 + 1] * 1024 + h];
    out[idx] = r;
}

// ---------------- launch ----------------
extern "C" void kernel_launch(void* const* d_in, const int* in_sizes, int n_in,
                              void* d_out, int out_size) {
    const float* x  = (const float*)d_in[0];   // [T, H]
    const float* rw = (const float*)d_in[1];   // [E, H]
    const float* wg = (const float*)d_in[2];   // [E, H, I]
    const float* wu = (const float*)d_in[3];   // [E, H, I]
    const float* wd = (const float*)d_in[4];   // [E, I, H]
    const float* sg = (const float*)d_in[5];   // [H, IS]
    const float* su = (const float*)d_in[6];   // [H, IS]
    const float* sd = (const float*)d_in[7];   // [IS, H]
    float* out = (float*)d_out;                // [T, H]

    // routing
    k_init<<<1, 32>>>();
    k_router<<<T, 128>>>(x, rw);
    k_scan<<<1, 32>>>();
    k_scatter<<<16, 256>>>();

    // shared expert (writes out with "=")
    k_shared_gateup<<<dim3(ISH / 32, T / BM, 1), 256>>>(x, sg, su);
    k_shared_down<<<dim3(H / BN, T / BM, 1), 256>>>(sd, out);

    // routed experts (expert-grouped)
    k_routed_gateup<<<dim3(IW / 32, T / BM, E), 256>>>(x, wg, wu);
    k_routed_down<<<dim3(H / BN, T / BM, E), 256>>>(wd);

    // final combine
    k_combine<<<(T * H + 255) / 256, 256>>>(out);
}